// round 2
// baseline (speedup 1.0000x reference)
#include <cuda_runtime.h>
#include <math.h>

// Problem constants
#define BB      4
#define TT      1024
#define DMODEL  2048
#define NHEADS  16
#define HDIM    128
#define MTOK    (BB * TT)        // 4096 tokens
#define NQKV    (3 * DMODEL)     // 6144

// Scratch (device globals: allocation-guard-safe)
__device__ float g_qkv[(size_t)MTOK * NQKV];    // [4096, 6144]
__device__ float g_att[(size_t)MTOK * DMODEL];  // [4096, 2048] merged-head attention output

// ---------------------------------------------------------------------------
// SGEMM with bias: C[M,N] = A[M,K] @ B[K,N] + bias[N]
// 128x128 block tile, BK=8, 256 threads, 8x8 register micro-tile.
// ---------------------------------------------------------------------------
__global__ __launch_bounds__(256, 1)
void sgemm_bias_kernel(const float* __restrict__ A, const float* __restrict__ B,
                       const float* __restrict__ bias, float* __restrict__ C,
                       int M, int N, int K)
{
    __shared__ float As[8][128];   // transposed: As[k][m]
    __shared__ float Bs[8][128];   // Bs[k][n]

    const int tid  = threadIdx.x;
    const int brow = blockIdx.y * 128;
    const int bcol = blockIdx.x * 128;
    const int tx   = tid & 15;
    const int ty   = tid >> 4;

    // global->shared load mapping
    const int arow = tid >> 1;           // 0..127
    const int acol = (tid & 1) << 2;     // 0 or 4
    const int brw  = tid >> 5;           // 0..7
    const int bcl  = (tid & 31) << 2;    // 0..124

    const float* Ap = A + (size_t)(brow + arow) * K + acol;
    const float* Bp = B + (size_t)brw * N + (bcol + bcl);

    float acc[8][8];
    #pragma unroll
    for (int j = 0; j < 8; ++j)
        #pragma unroll
        for (int i = 0; i < 8; ++i) acc[j][i] = 0.0f;

    for (int k0 = 0; k0 < K; k0 += 8) {
        float4 av = *(const float4*)(Ap + k0);
        float4 bv = *(const float4*)(Bp + (size_t)k0 * N);
        As[acol + 0][arow] = av.x;
        As[acol + 1][arow] = av.y;
        As[acol + 2][arow] = av.z;
        As[acol + 3][arow] = av.w;
        *(float4*)&Bs[brw][bcl] = bv;
        __syncthreads();

        #pragma unroll
        for (int k = 0; k < 8; ++k) {
            float a[8], b[8];
            *(float4*)(a)     = *(const float4*)&As[k][ty * 8];
            *(float4*)(a + 4) = *(const float4*)&As[k][ty * 8 + 4];
            *(float4*)(b)     = *(const float4*)&Bs[k][tx * 8];
            *(float4*)(b + 4) = *(const float4*)&Bs[k][tx * 8 + 4];
            #pragma unroll
            for (int j = 0; j < 8; ++j)
                #pragma unroll
                for (int i = 0; i < 8; ++i)
                    acc[j][i] = fmaf(a[j], b[i], acc[j][i]);
        }
        __syncthreads();
    }

    #pragma unroll
    for (int j = 0; j < 8; ++j) {
        const int r = brow + ty * 8 + j;
        float* Cp = C + (size_t)r * N + bcol + tx * 8;
        const float* bp = bias + bcol + tx * 8;
        #pragma unroll
        for (int i = 0; i < 8; i += 4) {
            float4 o;
            o.x = acc[j][i + 0] + bp[i + 0];
            o.y = acc[j][i + 1] + bp[i + 1];
            o.z = acc[j][i + 2] + bp[i + 2];
            o.w = acc[j][i + 3] + bp[i + 3];
            *(float4*)(Cp + i) = o;
        }
    }
}

// ---------------------------------------------------------------------------
// Flash attention (fp32, causal). One block = 64 queries of one (batch, head).
// 256 threads as 16x16 grid; thread (ty,tx) owns S rows {ty+16j}, cols {tx+16i}.
// Smem rows padded to 129 floats -> inner-loop K/V column reads are
// bank-conflict-free (129*16 mod 32 = 16; adjacent tx -> adjacent bank).
// NOTE: 129 stride => smem float4 stores would be misaligned for odd rows, so
// the global->smem staging does LDG.128 + 4x STS.32.
// ---------------------------------------------------------------------------
#define BQ    64
#define BKV   64
#define QSTR  129
#define PSTR  65
#define FLASH_SMEM_BYTES ((3 * BKV * QSTR + BQ * PSTR) * 4)  // 115712 B

__device__ __forceinline__ float redmax16(float v)
{
    #pragma unroll
    for (int o = 8; o > 0; o >>= 1)
        v = fmaxf(v, __shfl_xor_sync(0xffffffffu, v, o, 16));
    return v;
}
__device__ __forceinline__ float redsum16(float v)
{
    #pragma unroll
    for (int o = 8; o > 0; o >>= 1)
        v += __shfl_xor_sync(0xffffffffu, v, o, 16);
    return v;
}

__device__ __forceinline__ void store4(float* dst, float4 v)
{
    dst[0] = v.x; dst[1] = v.y; dst[2] = v.z; dst[3] = v.w;
}

__global__ __launch_bounds__(256, 1)
void flash_attn_kernel(const float* __restrict__ qkv, float* __restrict__ out)
{
    extern __shared__ float sm[];
    float* Qs = sm;                       // BQ  x QSTR
    float* Ks = Qs + BQ * QSTR;           // BKV x QSTR
    float* Vs = Ks + BKV * QSTR;          // BKV x QSTR
    float* Ps = Vs + BKV * QSTR;          // BQ  x PSTR

    const int tid = threadIdx.x;
    const int tx  = tid & 15;
    const int ty  = tid >> 4;
    const int qb  = blockIdx.x;           // query block 0..15
    const int bh  = blockIdx.y;           // 0..63
    const int b   = bh >> 4;
    const int h   = bh & 15;

    const float scale = 0.08838834764831845f;  // 1/sqrt(128)

    // Load Q tile [64, 128]
    {
        const float* src = qkv + (size_t)(b * TT + qb * BQ) * NQKV + h * HDIM;
        const int lr = tid >> 5;          // 0..7
        const int lc = (tid & 31) << 2;   // 0..124
        #pragma unroll
        for (int it = 0; it < 8; ++it) {
            const int r = lr + it * 8;
            float4 v = *(const float4*)(src + (size_t)r * NQKV + lc);
            store4(&Qs[r * QSTR + lc], v);
        }
    }

    float m_[4], l_[4], o_[4][8];
    #pragma unroll
    for (int j = 0; j < 4; ++j) {
        m_[j] = -1e30f;
        l_[j] = 0.0f;
        #pragma unroll
        for (int i = 0; i < 8; ++i) o_[j][i] = 0.0f;
    }

    for (int j = 0; j <= qb; ++j) {
        __syncthreads();  // prior iter done reading Ks/Vs/Ps; also covers Qs writes
        // Load K, V tiles [64, 128]
        {
            const size_t rowb = (size_t)(b * TT + j * BKV) * NQKV;
            const float* ksrc = qkv + rowb + DMODEL + h * HDIM;
            const float* vsrc = qkv + rowb + 2 * DMODEL + h * HDIM;
            const int lr = tid >> 5;
            const int lc = (tid & 31) << 2;
            #pragma unroll
            for (int it = 0; it < 8; ++it) {
                const int r = lr + it * 8;
                float4 kv = *(const float4*)(ksrc + (size_t)r * NQKV + lc);
                float4 vv = *(const float4*)(vsrc + (size_t)r * NQKV + lc);
                store4(&Ks[r * QSTR + lc], kv);
                store4(&Vs[r * QSTR + lc], vv);
            }
        }
        __syncthreads();

        // S = Q K^T  (4x4 per thread)
        float s[4][4];
        #pragma unroll
        for (int jj = 0; jj < 4; ++jj)
            #pragma unroll
            for (int ii = 0; ii < 4; ++ii) s[jj][ii] = 0.0f;

        #pragma unroll 4
        for (int k = 0; k < HDIM; ++k) {
            float qv[4], kv[4];
            #pragma unroll
            for (int jj = 0; jj < 4; ++jj) qv[jj] = Qs[(ty + 16 * jj) * QSTR + k];
            #pragma unroll
            for (int ii = 0; ii < 4; ++ii) kv[ii] = Ks[(tx + 16 * ii) * QSTR + k];
            #pragma unroll
            for (int jj = 0; jj < 4; ++jj)
                #pragma unroll
                for (int ii = 0; ii < 4; ++ii)
                    s[jj][ii] = fmaf(qv[jj], kv[ii], s[jj][ii]);
        }

        const bool diag = (j == qb);
        #pragma unroll
        for (int jj = 0; jj < 4; ++jj) {
            #pragma unroll
            for (int ii = 0; ii < 4; ++ii) {
                s[jj][ii] *= scale;
                if (diag) {
                    const int qg = qb * BQ + ty + 16 * jj;
                    const int kg = j * BKV + tx + 16 * ii;
                    if (kg > qg) s[jj][ii] = -1e30f;
                }
            }
        }

        // online softmax per row
        #pragma unroll
        for (int jj = 0; jj < 4; ++jj) {
            float mt = fmaxf(fmaxf(s[jj][0], s[jj][1]), fmaxf(s[jj][2], s[jj][3]));
            mt = redmax16(mt);
            const float mnew  = fmaxf(m_[jj], mt);
            const float alpha = __expf(m_[jj] - mnew);
            float ssum = 0.0f;
            #pragma unroll
            for (int ii = 0; ii < 4; ++ii) {
                const float p = __expf(s[jj][ii] - mnew);
                s[jj][ii] = p;
                ssum += p;
            }
            ssum = redsum16(ssum);
            l_[jj] = l_[jj] * alpha + ssum;
            m_[jj] = mnew;
            #pragma unroll
            for (int i = 0; i < 8; ++i) o_[jj][i] *= alpha;
            #pragma unroll
            for (int ii = 0; ii < 4; ++ii)
                Ps[(ty + 16 * jj) * PSTR + tx + 16 * ii] = s[jj][ii];
        }
        __syncthreads();

        // O += P @ V  (4 rows x 8 cols per thread)
        #pragma unroll 2
        for (int k = 0; k < BKV; ++k) {
            float vk[8];
            #pragma unroll
            for (int i = 0; i < 8; ++i) vk[i] = Vs[k * QSTR + tx + 16 * i];
            #pragma unroll
            for (int jj = 0; jj < 4; ++jj) {
                const float p = Ps[(ty + 16 * jj) * PSTR + k];
                #pragma unroll
                for (int i = 0; i < 8; ++i)
                    o_[jj][i] = fmaf(p, vk[i], o_[jj][i]);
            }
        }
    }

    // Write merged-head output [4096, 2048] at (b*T + q, h*128 + c)
    #pragma unroll
    for (int jj = 0; jj < 4; ++jj) {
        const float inv = 1.0f / l_[jj];
        const int r = qb * BQ + ty + 16 * jj;
        float* dst = out + (size_t)(b * TT + r) * DMODEL + h * HDIM;
        #pragma unroll
        for (int i = 0; i < 8; ++i)
            dst[tx + 16 * i] = o_[jj][i] * inv;
    }
}

// ---------------------------------------------------------------------------
extern "C" void kernel_launch(void* const* d_in, const int* in_sizes, int n_in,
                              void* d_out, int out_size)
{
    (void)in_sizes; (void)n_in; (void)out_size;
    const float* x      = (const float*)d_in[0];
    const float* w_qkv  = (const float*)d_in[1];
    const float* b_qkv  = (const float*)d_in[2];
    const float* w_out  = (const float*)d_in[3];
    const float* b_out  = (const float*)d_in[4];
    float* out          = (float*)d_out;

    void* qkvp = nullptr;
    void* attp = nullptr;
    cudaGetSymbolAddress(&qkvp, g_qkv);
    cudaGetSymbolAddress(&attp, g_att);

    cudaFuncSetAttribute(flash_attn_kernel,
                         cudaFuncAttributeMaxDynamicSharedMemorySize,
                         FLASH_SMEM_BYTES);

    // 1) QKV projection: [4096,2048] @ [2048,6144] + b
    {
        dim3 grid(NQKV / 128, MTOK / 128);
        sgemm_bias_kernel<<<grid, 256>>>(x, w_qkv, b_qkv, (float*)qkvp,
                                         MTOK, NQKV, DMODEL);
    }
    // 2) Causal flash attention per (batch, head)
    {
        dim3 grid(TT / BQ, BB * NHEADS);
        flash_attn_kernel<<<grid, 256, FLASH_SMEM_BYTES>>>((const float*)qkvp,
                                                           (float*)attp);
    }
    // 3) Output projection: [4096,2048] @ [2048,2048] + b
    {
        dim3 grid(DMODEL / 128, MTOK / 128);
        sgemm_bias_kernel<<<grid, 256>>>((const float*)attp, w_out, b_out, out,
                                         MTOK, DMODEL, DMODEL);
    }
}

// round 4
// speedup vs baseline: 2.9355x; 2.9355x over previous
#include <cuda_runtime.h>
#include <cuda_bf16.h>
#include <math.h>
#include <stdint.h>

// Problem constants
#define BB      4
#define TT      1024
#define DMODEL  2048
#define NHEADS  16
#define HDIM    128
#define MTOK    (BB * TT)        // 4096 tokens
#define NQKV    (3 * DMODEL)     // 6144
#define GK      2048             // GEMM K (both GEMMs)

// ---------------------------------------------------------------------------
// Scratch (device globals: allocation-guard-safe)
// ---------------------------------------------------------------------------
__device__ float g_qkv[(size_t)MTOK * NQKV];
__device__ float g_att[(size_t)MTOK * DMODEL];
__device__ __nv_bfloat16 g_xh[(size_t)MTOK * DMODEL];
__device__ __nv_bfloat16 g_xl[(size_t)MTOK * DMODEL];
__device__ __nv_bfloat16 g_wqt_h[(size_t)NQKV * DMODEL];   // w_qkv^T [6144,2048]
__device__ __nv_bfloat16 g_wqt_l[(size_t)NQKV * DMODEL];
__device__ __nv_bfloat16 g_wot_h[(size_t)DMODEL * DMODEL]; // w_out^T [2048,2048]
__device__ __nv_bfloat16 g_wot_l[(size_t)DMODEL * DMODEL];
__device__ __nv_bfloat16 g_ath[(size_t)MTOK * DMODEL];
__device__ __nv_bfloat16 g_atl[(size_t)MTOK * DMODEL];

// ---------------------------------------------------------------------------
// PTX helpers — all non-"a" instructions (sm_80-class): cp.async, ldmatrix, mma
// ---------------------------------------------------------------------------
__device__ __forceinline__ uint32_t smem_u32(const void* p) {
    uint32_t a;
    asm("{ .reg .u64 t; cvta.to.shared.u64 t, %1; cvt.u32.u64 %0, t; }" : "=r"(a) : "l"(p));
    return a;
}
__device__ __forceinline__ void cp16(uint32_t dst, const void* src) {
    asm volatile("cp.async.cg.shared.global [%0], [%1], 16;"
                 :: "r"(dst), "l"(__cvta_generic_to_global(src)) : "memory");
}
__device__ __forceinline__ void cp_commit() { asm volatile("cp.async.commit_group;" ::: "memory"); }
__device__ __forceinline__ void cp_wait0()  { asm volatile("cp.async.wait_group 0;" ::: "memory"); }
__device__ __forceinline__ void cp_wait1()  { asm volatile("cp.async.wait_group 1;" ::: "memory"); }

__device__ __forceinline__ void ldsm4(uint32_t (&r)[4], uint32_t addr) {
    asm volatile("ldmatrix.sync.aligned.m8n8.x4.shared.b16 {%0,%1,%2,%3}, [%4];"
                 : "=r"(r[0]), "=r"(r[1]), "=r"(r[2]), "=r"(r[3]) : "r"(addr));
}
__device__ __forceinline__ void mma16816(float (&d)[4], const uint32_t (&a)[4],
                                         uint32_t b0, uint32_t b1) {
    asm volatile("mma.sync.aligned.m16n8k16.row.col.f32.bf16.bf16.f32 "
                 "{%0,%1,%2,%3}, {%4,%5,%6,%7}, {%8,%9}, {%0,%1,%2,%3};"
                 : "+f"(d[0]), "+f"(d[1]), "+f"(d[2]), "+f"(d[3])
                 : "r"(a[0]), "r"(a[1]), "r"(a[2]), "r"(a[3]), "r"(b0), "r"(b1));
}

// ---------------------------------------------------------------------------
// Split fp32 -> bf16 hi + bf16 lo
// ---------------------------------------------------------------------------
__global__ void split_kernel(const float* __restrict__ in,
                             __nv_bfloat16* __restrict__ hi,
                             __nv_bfloat16* __restrict__ lo, int n4)
{
    int i = blockIdx.x * blockDim.x + threadIdx.x;
    if (i >= n4) return;
    float4 v = ((const float4*)in)[i];
    float f[4] = {v.x, v.y, v.z, v.w};
    ushort4 H, L;
    unsigned short* hp = &H.x;
    unsigned short* lp = &L.x;
    #pragma unroll
    for (int j = 0; j < 4; ++j) {
        __nv_bfloat16 h = __float2bfloat16(f[j]);
        __nv_bfloat16 l = __float2bfloat16(f[j] - __bfloat162float(h));
        hp[j] = __bfloat16_as_ushort(h);
        lp[j] = __bfloat16_as_ushort(l);
    }
    ((ushort4*)hi)[i] = H;
    ((ushort4*)lo)[i] = L;
}

// ---------------------------------------------------------------------------
// Transpose + split: W [K,N] fp32 -> Wt hi/lo [N,K] bf16
// ---------------------------------------------------------------------------
__global__ void transpose_split_kernel(const float* __restrict__ W,
                                       __nv_bfloat16* __restrict__ Th,
                                       __nv_bfloat16* __restrict__ Tl,
                                       int K, int N)
{
    __shared__ float t[32][33];
    const int tx = threadIdx.x, ty = threadIdx.y;
    const int n0 = blockIdx.x * 32, k0 = blockIdx.y * 32;
    #pragma unroll
    for (int i = 0; i < 4; ++i)
        t[ty + 8 * i][tx] = W[(size_t)(k0 + ty + 8 * i) * N + n0 + tx];
    __syncthreads();
    #pragma unroll
    for (int i = 0; i < 4; ++i) {
        float v = t[tx][ty + 8 * i];
        __nv_bfloat16 h = __float2bfloat16(v);
        __nv_bfloat16 l = __float2bfloat16(v - __bfloat162float(h));
        const size_t o = (size_t)(n0 + ty + 8 * i) * K + k0 + tx;
        Th[o] = h;
        Tl[o] = l;
    }
}

// ---------------------------------------------------------------------------
// bf16x3 GEMM via mma.sync: C[M,N] = Ah@Bh^T + Ah@Bl^T + Al@Bh^T + bias
// A hi/lo: [M,2048] K-major. B hi/lo: [N,2048] K-major (pre-transposed).
// CTA tile 128x128, BK=32, 3-stage cp.async pipeline, 8 warps (warp 32x64).
// Smem tile row = 64B (32 bf16), 4x16B chunks, XOR-swizzled: chunk' = s^(r&3).
// ---------------------------------------------------------------------------
#define BK        32
#define NCHUNK    (GK / BK)       // 64
#define STAGES    3
#define TILE_BYTES  8192          // 128 rows x 64 B
#define AH_OFF    0
#define AL_OFF    8192
#define BH_OFF    16384
#define BL_OFF    24576
#define STAGE_BYTES 32768
#define GSMEM     (STAGES * STAGE_BYTES)   // 98304

__device__ __forceinline__ uint32_t swz(int r, int s) {
    return (uint32_t)(r * 64 + ((s ^ (r & 3)) << 4));
}

__device__ __forceinline__ void load_stage(uint32_t sb, int stage,
                                           const __nv_bfloat16* __restrict__ Ah,
                                           const __nv_bfloat16* __restrict__ Al,
                                           const __nv_bfloat16* __restrict__ Bh,
                                           const __nv_bfloat16* __restrict__ Bl,
                                           int brow, int bcol, int k0, int tid)
{
    const uint32_t base = sb + (uint32_t)stage * STAGE_BYTES;
    const int idx = tid * 2;                 // two 16B segs per thread per tile
    const int r = idx >> 2, s = idx & 3;     // s in {0, 2}
    const uint32_t o0 = swz(r, s), o1 = swz(r, s + 1);

    const __nv_bfloat16* a = Ah + (size_t)(brow + r) * GK + k0 + s * 8;
    cp16(base + AH_OFF + o0, a);
    cp16(base + AH_OFF + o1, a + 8);
    a = Al + (size_t)(brow + r) * GK + k0 + s * 8;
    cp16(base + AL_OFF + o0, a);
    cp16(base + AL_OFF + o1, a + 8);
    a = Bh + (size_t)(bcol + r) * GK + k0 + s * 8;
    cp16(base + BH_OFF + o0, a);
    cp16(base + BH_OFF + o1, a + 8);
    a = Bl + (size_t)(bcol + r) * GK + k0 + s * 8;
    cp16(base + BL_OFF + o0, a);
    cp16(base + BL_OFF + o1, a + 8);
    cp_commit();
}

__global__ __launch_bounds__(256)
void gemm_bf16x3_kernel(const __nv_bfloat16* __restrict__ Ah,
                        const __nv_bfloat16* __restrict__ Al,
                        const __nv_bfloat16* __restrict__ Bh,
                        const __nv_bfloat16* __restrict__ Bl,
                        const float* __restrict__ bias,
                        float* __restrict__ C, int N)
{
    extern __shared__ char smem[];
    const uint32_t sb = smem_u32(smem);
    const int tid  = threadIdx.x;
    const int lane = tid & 31;
    const int wid  = tid >> 5;
    const int wm   = wid >> 1;               // 0..3 -> m offset 32*wm
    const int wn   = wid & 1;                // 0..1 -> n offset 64*wn
    const int brow = blockIdx.y * 128;
    const int bcol = blockIdx.x * 128;
    const int m0   = wm * 32;
    const int n0   = wn * 64;

    float acc[2][8][4];
    #pragma unroll
    for (int mt = 0; mt < 2; ++mt)
        #pragma unroll
        for (int nt = 0; nt < 8; ++nt)
            #pragma unroll
            for (int i = 0; i < 4; ++i) acc[mt][nt][i] = 0.0f;

    load_stage(sb, 0, Ah, Al, Bh, Bl, brow, bcol, 0, tid);
    load_stage(sb, 1, Ah, Al, Bh, Bl, brow, bcol, BK, tid);

    for (int c = 0; c < NCHUNK; ++c) {
        if (c + 1 < NCHUNK) cp_wait1(); else cp_wait0();
        __syncthreads();
        if (c + 2 < NCHUNK)
            load_stage(sb, (c + 2) % STAGES, Ah, Al, Bh, Bl, brow, bcol,
                       (c + 2) * BK, tid);

        const uint32_t st = sb + (uint32_t)(c % STAGES) * STAGE_BYTES;
        #pragma unroll
        for (int h = 0; h < 2; ++h) {
            uint32_t aH[2][4], aL[2][4], bH[4][4], bL[4][4];
            const int seg = 2 * h + (lane >> 4);
            #pragma unroll
            for (int mt = 0; mt < 2; ++mt) {
                const int r = m0 + mt * 16 + (lane & 15);
                const uint32_t ad = st + swz(r, seg);
                ldsm4(aH[mt], ad + AH_OFF);
                ldsm4(aL[mt], ad + AL_OFF);
            }
            #pragma unroll
            for (int p = 0; p < 4; ++p) {
                const int r = n0 + p * 16 + (lane & 15);
                const uint32_t bd = st + swz(r, seg);
                ldsm4(bH[p], bd + BH_OFF);
                ldsm4(bL[p], bd + BL_OFF);
            }
            #pragma unroll
            for (int mt = 0; mt < 2; ++mt)
                #pragma unroll
                for (int nt = 0; nt < 8; ++nt) {
                    const int p = nt >> 1, sub = nt & 1;
                    mma16816(acc[mt][nt], aH[mt], bH[p][sub], bH[p][sub + 2]);
                    mma16816(acc[mt][nt], aH[mt], bL[p][sub], bL[p][sub + 2]);
                    mma16816(acc[mt][nt], aL[mt], bH[p][sub], bH[p][sub + 2]);
                }
        }
        __syncthreads();
    }

    // Epilogue: fragment -> global fp32 + bias
    #pragma unroll
    for (int mt = 0; mt < 2; ++mt) {
        const int r0 = brow + m0 + mt * 16 + (lane >> 2);
        #pragma unroll
        for (int nt = 0; nt < 8; ++nt) {
            const int col = bcol + n0 + nt * 8 + (lane & 3) * 2;
            const float b0 = bias[col], b1 = bias[col + 1];
            float2* p0 = (float2*)(C + (size_t)r0 * N + col);
            float2* p1 = (float2*)(C + (size_t)(r0 + 8) * N + col);
            *p0 = make_float2(acc[mt][nt][0] + b0, acc[mt][nt][1] + b1);
            *p1 = make_float2(acc[mt][nt][2] + b0, acc[mt][nt][3] + b1);
        }
    }
}

// ---------------------------------------------------------------------------
// Flash attention (fp32, causal) — unchanged passing version.
// ---------------------------------------------------------------------------
#define BQ    64
#define BKV   64
#define QSTR  129
#define PSTR  65
#define FLASH_SMEM_BYTES ((3 * BKV * QSTR + BQ * PSTR) * 4)  // 115712 B

__device__ __forceinline__ float redmax16(float v)
{
    #pragma unroll
    for (int o = 8; o > 0; o >>= 1)
        v = fmaxf(v, __shfl_xor_sync(0xffffffffu, v, o, 16));
    return v;
}
__device__ __forceinline__ float redsum16(float v)
{
    #pragma unroll
    for (int o = 8; o > 0; o >>= 1)
        v += __shfl_xor_sync(0xffffffffu, v, o, 16);
    return v;
}
__device__ __forceinline__ void store4(float* dst, float4 v)
{
    dst[0] = v.x; dst[1] = v.y; dst[2] = v.z; dst[3] = v.w;
}

__global__ __launch_bounds__(256, 1)
void flash_attn_kernel(const float* __restrict__ qkv, float* __restrict__ out)
{
    extern __shared__ float sm[];
    float* Qs = sm;
    float* Ks = Qs + BQ * QSTR;
    float* Vs = Ks + BKV * QSTR;
    float* Ps = Vs + BKV * QSTR;

    const int tid = threadIdx.x;
    const int tx  = tid & 15;
    const int ty  = tid >> 4;
    const int qb  = blockIdx.x;
    const int bh  = blockIdx.y;
    const int b   = bh >> 4;
    const int h   = bh & 15;

    const float scale = 0.08838834764831845f;

    {
        const float* src = qkv + (size_t)(b * TT + qb * BQ) * NQKV + h * HDIM;
        const int lr = tid >> 5;
        const int lc = (tid & 31) << 2;
        #pragma unroll
        for (int it = 0; it < 8; ++it) {
            const int r = lr + it * 8;
            float4 v = *(const float4*)(src + (size_t)r * NQKV + lc);
            store4(&Qs[r * QSTR + lc], v);
        }
    }

    float m_[4], l_[4], o_[4][8];
    #pragma unroll
    for (int j = 0; j < 4; ++j) {
        m_[j] = -1e30f;
        l_[j] = 0.0f;
        #pragma unroll
        for (int i = 0; i < 8; ++i) o_[j][i] = 0.0f;
    }

    for (int j = 0; j <= qb; ++j) {
        __syncthreads();
        {
            const size_t rowb = (size_t)(b * TT + j * BKV) * NQKV;
            const float* ksrc = qkv + rowb + DMODEL + h * HDIM;
            const float* vsrc = qkv + rowb + 2 * DMODEL + h * HDIM;
            const int lr = tid >> 5;
            const int lc = (tid & 31) << 2;
            #pragma unroll
            for (int it = 0; it < 8; ++it) {
                const int r = lr + it * 8;
                float4 kv = *(const float4*)(ksrc + (size_t)r * NQKV + lc);
                float4 vv = *(const float4*)(vsrc + (size_t)r * NQKV + lc);
                store4(&Ks[r * QSTR + lc], kv);
                store4(&Vs[r * QSTR + lc], vv);
            }
        }
        __syncthreads();

        float s[4][4];
        #pragma unroll
        for (int jj = 0; jj < 4; ++jj)
            #pragma unroll
            for (int ii = 0; ii < 4; ++ii) s[jj][ii] = 0.0f;

        #pragma unroll 4
        for (int k = 0; k < HDIM; ++k) {
            float qv[4], kv[4];
            #pragma unroll
            for (int jj = 0; jj < 4; ++jj) qv[jj] = Qs[(ty + 16 * jj) * QSTR + k];
            #pragma unroll
            for (int ii = 0; ii < 4; ++ii) kv[ii] = Ks[(tx + 16 * ii) * QSTR + k];
            #pragma unroll
            for (int jj = 0; jj < 4; ++jj)
                #pragma unroll
                for (int ii = 0; ii < 4; ++ii)
                    s[jj][ii] = fmaf(qv[jj], kv[ii], s[jj][ii]);
        }

        const bool diag = (j == qb);
        #pragma unroll
        for (int jj = 0; jj < 4; ++jj) {
            #pragma unroll
            for (int ii = 0; ii < 4; ++ii) {
                s[jj][ii] *= scale;
                if (diag) {
                    const int qg = qb * BQ + ty + 16 * jj;
                    const int kg = j * BKV + tx + 16 * ii;
                    if (kg > qg) s[jj][ii] = -1e30f;
                }
            }
        }

        #pragma unroll
        for (int jj = 0; jj < 4; ++jj) {
            float mt = fmaxf(fmaxf(s[jj][0], s[jj][1]), fmaxf(s[jj][2], s[jj][3]));
            mt = redmax16(mt);
            const float mnew  = fmaxf(m_[jj], mt);
            const float alpha = __expf(m_[jj] - mnew);
            float ssum = 0.0f;
            #pragma unroll
            for (int ii = 0; ii < 4; ++ii) {
                const float p = __expf(s[jj][ii] - mnew);
                s[jj][ii] = p;
                ssum += p;
            }
            ssum = redsum16(ssum);
            l_[jj] = l_[jj] * alpha + ssum;
            m_[jj] = mnew;
            #pragma unroll
            for (int i = 0; i < 8; ++i) o_[jj][i] *= alpha;
            #pragma unroll
            for (int ii = 0; ii < 4; ++ii)
                Ps[(ty + 16 * jj) * PSTR + tx + 16 * ii] = s[jj][ii];
        }
        __syncthreads();

        #pragma unroll 2
        for (int k = 0; k < BKV; ++k) {
            float vk[8];
            #pragma unroll
            for (int i = 0; i < 8; ++i) vk[i] = Vs[k * QSTR + tx + 16 * i];
            #pragma unroll
            for (int jj = 0; jj < 4; ++jj) {
                const float p = Ps[(ty + 16 * jj) * PSTR + k];
                #pragma unroll
                for (int i = 0; i < 8; ++i)
                    o_[jj][i] = fmaf(p, vk[i], o_[jj][i]);
            }
        }
    }

    #pragma unroll
    for (int jj = 0; jj < 4; ++jj) {
        const float inv = 1.0f / l_[jj];
        const int r = qb * BQ + ty + 16 * jj;
        float* dst = out + (size_t)(b * TT + r) * DMODEL + h * HDIM;
        #pragma unroll
        for (int i = 0; i < 8; ++i)
            dst[tx + 16 * i] = o_[jj][i] * inv;
    }
}

// ---------------------------------------------------------------------------
extern "C" void kernel_launch(void* const* d_in, const int* in_sizes, int n_in,
                              void* d_out, int out_size)
{
    (void)in_sizes; (void)n_in; (void)out_size;
    const float* x      = (const float*)d_in[0];
    const float* w_qkv  = (const float*)d_in[1];
    const float* b_qkv  = (const float*)d_in[2];
    const float* w_out  = (const float*)d_in[3];
    const float* b_out  = (const float*)d_in[4];
    float* out          = (float*)d_out;

    void *qkvp, *attp, *xh, *xl, *wqh, *wql, *woh, *wol, *ath, *atl;
    cudaGetSymbolAddress(&qkvp, g_qkv);
    cudaGetSymbolAddress(&attp, g_att);
    cudaGetSymbolAddress(&xh, g_xh);
    cudaGetSymbolAddress(&xl, g_xl);
    cudaGetSymbolAddress(&wqh, g_wqt_h);
    cudaGetSymbolAddress(&wql, g_wqt_l);
    cudaGetSymbolAddress(&woh, g_wot_h);
    cudaGetSymbolAddress(&wol, g_wot_l);
    cudaGetSymbolAddress(&ath, g_ath);
    cudaGetSymbolAddress(&atl, g_atl);

    cudaFuncSetAttribute(flash_attn_kernel,
                         cudaFuncAttributeMaxDynamicSharedMemorySize, FLASH_SMEM_BYTES);
    cudaFuncSetAttribute(gemm_bf16x3_kernel,
                         cudaFuncAttributeMaxDynamicSharedMemorySize, GSMEM);

    // Split x into bf16 hi/lo
    {
        const int n4 = MTOK * DMODEL / 4;
        split_kernel<<<(n4 + 255) / 256, 256>>>(x, (__nv_bfloat16*)xh,
                                                (__nv_bfloat16*)xl, n4);
    }
    // Transpose + split weights
    {
        dim3 blk(32, 8);
        transpose_split_kernel<<<dim3(NQKV / 32, DMODEL / 32), blk>>>(
            w_qkv, (__nv_bfloat16*)wqh, (__nv_bfloat16*)wql, DMODEL, NQKV);
        transpose_split_kernel<<<dim3(DMODEL / 32, DMODEL / 32), blk>>>(
            w_out, (__nv_bfloat16*)woh, (__nv_bfloat16*)wol, DMODEL, DMODEL);
    }
    // 1) QKV projection (tensor cores via mma.sync)
    {
        dim3 grid(NQKV / 128, MTOK / 128);
        gemm_bf16x3_kernel<<<grid, 256, GSMEM>>>(
            (const __nv_bfloat16*)xh, (const __nv_bfloat16*)xl,
            (const __nv_bfloat16*)wqh, (const __nv_bfloat16*)wql,
            b_qkv, (float*)qkvp, NQKV);
    }
    // 2) Causal flash attention
    {
        dim3 grid(TT / BQ, BB * NHEADS);
        flash_attn_kernel<<<grid, 256, FLASH_SMEM_BYTES>>>((const float*)qkvp,
                                                           (float*)attp);
    }
    // Split attention output
    {
        const int n4 = MTOK * DMODEL / 4;
        split_kernel<<<(n4 + 255) / 256, 256>>>((const float*)attp,
                                                (__nv_bfloat16*)ath,
                                                (__nv_bfloat16*)atl, n4);
    }
    // 3) Output projection (tensor cores via mma.sync)
    {
        dim3 grid(DMODEL / 128, MTOK / 128);
        gemm_bf16x3_kernel<<<grid, 256, GSMEM>>>(
            (const __nv_bfloat16*)ath, (const __nv_bfloat16*)atl,
            (const __nv_bfloat16*)woh, (const __nv_bfloat16*)wol,
            b_out, out, DMODEL);
    }
}

// round 5
// speedup vs baseline: 3.8471x; 1.3105x over previous
#include <cuda_runtime.h>
#include <cuda_bf16.h>
#include <math.h>
#include <stdint.h>

// Problem constants
#define BB      4
#define TT      1024
#define DMODEL  2048
#define NHEADS  16
#define HDIM    128
#define MTOK    (BB * TT)        // 4096
#define NQKV    (3 * DMODEL)     // 6144
#define GK      2048

// ---------------------------------------------------------------------------
// Scratch (device globals)
// ---------------------------------------------------------------------------
__device__ __nv_bfloat16 g_xh[(size_t)MTOK * DMODEL];
__device__ __nv_bfloat16 g_xl[(size_t)MTOK * DMODEL];
__device__ __nv_bfloat16 g_wqt_h[(size_t)NQKV * DMODEL];   // w_qkv^T [6144,2048]
__device__ __nv_bfloat16 g_wqt_l[(size_t)NQKV * DMODEL];
__device__ __nv_bfloat16 g_wot_h[(size_t)DMODEL * DMODEL]; // w_out^T [2048,2048]
__device__ __nv_bfloat16 g_wot_l[(size_t)DMODEL * DMODEL];
__device__ __nv_bfloat16 g_qkvh[(size_t)MTOK * NQKV];      // QKV bf16 hi/lo
__device__ __nv_bfloat16 g_qkvl[(size_t)MTOK * NQKV];
__device__ __nv_bfloat16 g_ath[(size_t)MTOK * DMODEL];     // attention out hi/lo
__device__ __nv_bfloat16 g_atl[(size_t)MTOK * DMODEL];

// ---------------------------------------------------------------------------
// PTX helpers (all sm_80-class: legal on plain compute_103)
// ---------------------------------------------------------------------------
__device__ __forceinline__ uint32_t smem_u32(const void* p) {
    uint32_t a;
    asm("{ .reg .u64 t; cvta.to.shared.u64 t, %1; cvt.u32.u64 %0, t; }" : "=r"(a) : "l"(p));
    return a;
}
__device__ __forceinline__ void cp16(uint32_t dst, const void* src) {
    asm volatile("cp.async.cg.shared.global [%0], [%1], 16;"
                 :: "r"(dst), "l"(__cvta_generic_to_global(src)) : "memory");
}
__device__ __forceinline__ void cp_commit() { asm volatile("cp.async.commit_group;" ::: "memory"); }
__device__ __forceinline__ void cp_wait0()  { asm volatile("cp.async.wait_group 0;" ::: "memory"); }
__device__ __forceinline__ void cp_wait1()  { asm volatile("cp.async.wait_group 1;" ::: "memory"); }

__device__ __forceinline__ void ldsm4(uint32_t (&r)[4], uint32_t addr) {
    asm volatile("ldmatrix.sync.aligned.m8n8.x4.shared.b16 {%0,%1,%2,%3}, [%4];"
                 : "=r"(r[0]), "=r"(r[1]), "=r"(r[2]), "=r"(r[3]) : "r"(addr));
}
__device__ __forceinline__ void ldsm4t(uint32_t (&r)[4], uint32_t addr) {
    asm volatile("ldmatrix.sync.aligned.m8n8.x4.trans.shared.b16 {%0,%1,%2,%3}, [%4];"
                 : "=r"(r[0]), "=r"(r[1]), "=r"(r[2]), "=r"(r[3]) : "r"(addr));
}
__device__ __forceinline__ void mma16816(float (&d)[4], const uint32_t (&a)[4],
                                         uint32_t b0, uint32_t b1) {
    asm volatile("mma.sync.aligned.m16n8k16.row.col.f32.bf16.bf16.f32 "
                 "{%0,%1,%2,%3}, {%4,%5,%6,%7}, {%8,%9}, {%0,%1,%2,%3};"
                 : "+f"(d[0]), "+f"(d[1]), "+f"(d[2]), "+f"(d[3])
                 : "r"(a[0]), "r"(a[1]), "r"(a[2]), "r"(a[3]), "r"(b0), "r"(b1));
}
// pack bf16(x) low | bf16(y) high; also produce the lo-residual pack
__device__ __forceinline__ void split_pack2(float x, float y, uint32_t& hp, uint32_t& lp) {
    __nv_bfloat16 hx = __float2bfloat16(x), hy = __float2bfloat16(y);
    float rx = x - __bfloat162float(hx), ry = y - __bfloat162float(hy);
    __nv_bfloat16 lx = __float2bfloat16(rx), ly = __float2bfloat16(ry);
    hp = (uint32_t)__bfloat16_as_ushort(hx) | ((uint32_t)__bfloat16_as_ushort(hy) << 16);
    lp = (uint32_t)__bfloat16_as_ushort(lx) | ((uint32_t)__bfloat16_as_ushort(ly) << 16);
}

// ---------------------------------------------------------------------------
// Split fp32 -> bf16 hi + lo
// ---------------------------------------------------------------------------
__global__ void split_kernel(const float* __restrict__ in,
                             __nv_bfloat16* __restrict__ hi,
                             __nv_bfloat16* __restrict__ lo, int n4)
{
    int i = blockIdx.x * blockDim.x + threadIdx.x;
    if (i >= n4) return;
    float4 v = ((const float4*)in)[i];
    float f[4] = {v.x, v.y, v.z, v.w};
    ushort4 H, L;
    unsigned short* hp = &H.x;
    unsigned short* lp = &L.x;
    #pragma unroll
    for (int j = 0; j < 4; ++j) {
        __nv_bfloat16 h = __float2bfloat16(f[j]);
        __nv_bfloat16 l = __float2bfloat16(f[j] - __bfloat162float(h));
        hp[j] = __bfloat16_as_ushort(h);
        lp[j] = __bfloat16_as_ushort(l);
    }
    ((ushort4*)hi)[i] = H;
    ((ushort4*)lo)[i] = L;
}

// ---------------------------------------------------------------------------
// Transpose + split: W [K,N] fp32 -> Wt hi/lo [N,K] bf16
// ---------------------------------------------------------------------------
__global__ void transpose_split_kernel(const float* __restrict__ W,
                                       __nv_bfloat16* __restrict__ Th,
                                       __nv_bfloat16* __restrict__ Tl,
                                       int K, int N)
{
    __shared__ float t[32][33];
    const int tx = threadIdx.x, ty = threadIdx.y;
    const int n0 = blockIdx.x * 32, k0 = blockIdx.y * 32;
    #pragma unroll
    for (int i = 0; i < 4; ++i)
        t[ty + 8 * i][tx] = W[(size_t)(k0 + ty + 8 * i) * N + n0 + tx];
    __syncthreads();
    #pragma unroll
    for (int i = 0; i < 4; ++i) {
        float v = t[tx][ty + 8 * i];
        __nv_bfloat16 h = __float2bfloat16(v);
        __nv_bfloat16 l = __float2bfloat16(v - __bfloat162float(h));
        const size_t o = (size_t)(n0 + ty + 8 * i) * K + k0 + tx;
        Th[o] = h;
        Tl[o] = l;
    }
}

// ---------------------------------------------------------------------------
// bf16x3 GEMM via mma.sync. Template epilogue:
//   SPLIT=false: C fp32 = acc + bias
//   SPLIT=true : Ch/Cl bf16 hi/lo of (acc + bias)
// ---------------------------------------------------------------------------
#define BKG       32
#define NCHUNK    (GK / BKG)      // 64
#define STAGES    3
#define AH_OFF    0
#define AL_OFF    8192
#define BH_OFF    16384
#define BL_OFF    24576
#define STAGE_BYTES 32768
#define GSMEM     (STAGES * STAGE_BYTES)   // 98304

__device__ __forceinline__ uint32_t swz(int r, int s) {
    return (uint32_t)(r * 64 + ((s ^ (r & 3)) << 4));
}

__device__ __forceinline__ void load_stage(uint32_t sb, int stage,
                                           const __nv_bfloat16* __restrict__ Ah,
                                           const __nv_bfloat16* __restrict__ Al,
                                           const __nv_bfloat16* __restrict__ Bh,
                                           const __nv_bfloat16* __restrict__ Bl,
                                           int brow, int bcol, int k0, int tid)
{
    const uint32_t base = sb + (uint32_t)stage * STAGE_BYTES;
    const int idx = tid * 2;
    const int r = idx >> 2, s = idx & 3;
    const uint32_t o0 = swz(r, s), o1 = swz(r, s + 1);

    const __nv_bfloat16* a = Ah + (size_t)(brow + r) * GK + k0 + s * 8;
    cp16(base + AH_OFF + o0, a);
    cp16(base + AH_OFF + o1, a + 8);
    a = Al + (size_t)(brow + r) * GK + k0 + s * 8;
    cp16(base + AL_OFF + o0, a);
    cp16(base + AL_OFF + o1, a + 8);
    a = Bh + (size_t)(bcol + r) * GK + k0 + s * 8;
    cp16(base + BH_OFF + o0, a);
    cp16(base + BH_OFF + o1, a + 8);
    a = Bl + (size_t)(bcol + r) * GK + k0 + s * 8;
    cp16(base + BL_OFF + o0, a);
    cp16(base + BL_OFF + o1, a + 8);
    cp_commit();
}

template <bool SPLIT>
__global__ __launch_bounds__(256, 2)
void gemm_bf16x3_kernel(const __nv_bfloat16* __restrict__ Ah,
                        const __nv_bfloat16* __restrict__ Al,
                        const __nv_bfloat16* __restrict__ Bh,
                        const __nv_bfloat16* __restrict__ Bl,
                        const float* __restrict__ bias,
                        float* __restrict__ C,
                        __nv_bfloat16* __restrict__ Ch,
                        __nv_bfloat16* __restrict__ Cl, int N)
{
    extern __shared__ char smem[];
    const uint32_t sb = smem_u32(smem);
    const int tid  = threadIdx.x;
    const int lane = tid & 31;
    const int wid  = tid >> 5;
    const int wm   = wid >> 1;
    const int wn   = wid & 1;
    const int brow = blockIdx.y * 128;
    const int bcol = blockIdx.x * 128;
    const int m0   = wm * 32;
    const int n0   = wn * 64;

    float acc[2][8][4];
    #pragma unroll
    for (int mt = 0; mt < 2; ++mt)
        #pragma unroll
        for (int nt = 0; nt < 8; ++nt)
            #pragma unroll
            for (int i = 0; i < 4; ++i) acc[mt][nt][i] = 0.0f;

    load_stage(sb, 0, Ah, Al, Bh, Bl, brow, bcol, 0, tid);
    load_stage(sb, 1, Ah, Al, Bh, Bl, brow, bcol, BKG, tid);

    for (int c = 0; c < NCHUNK; ++c) {
        if (c + 1 < NCHUNK) cp_wait1(); else cp_wait0();
        __syncthreads();
        if (c + 2 < NCHUNK)
            load_stage(sb, (c + 2) % STAGES, Ah, Al, Bh, Bl, brow, bcol,
                       (c + 2) * BKG, tid);

        const uint32_t st = sb + (uint32_t)(c % STAGES) * STAGE_BYTES;
        #pragma unroll
        for (int hh = 0; hh < 2; ++hh) {
            uint32_t aH[2][4], aL[2][4], bH[4][4], bL[4][4];
            const int seg = 2 * hh + (lane >> 4);
            #pragma unroll
            for (int mt = 0; mt < 2; ++mt) {
                const int r = m0 + mt * 16 + (lane & 15);
                const uint32_t ad = st + swz(r, seg);
                ldsm4(aH[mt], ad + AH_OFF);
                ldsm4(aL[mt], ad + AL_OFF);
            }
            #pragma unroll
            for (int p = 0; p < 4; ++p) {
                const int r = n0 + p * 16 + (lane & 15);
                const uint32_t bd = st + swz(r, seg);
                ldsm4(bH[p], bd + BH_OFF);
                ldsm4(bL[p], bd + BL_OFF);
            }
            #pragma unroll
            for (int mt = 0; mt < 2; ++mt)
                #pragma unroll
                for (int nt = 0; nt < 8; ++nt) {
                    const int p = nt >> 1, sub = nt & 1;
                    mma16816(acc[mt][nt], aH[mt], bH[p][sub], bH[p][sub + 2]);
                    mma16816(acc[mt][nt], aH[mt], bL[p][sub], bL[p][sub + 2]);
                    mma16816(acc[mt][nt], aL[mt], bH[p][sub], bH[p][sub + 2]);
                }
        }
        __syncthreads();
    }

    #pragma unroll
    for (int mt = 0; mt < 2; ++mt) {
        const int r0 = brow + m0 + mt * 16 + (lane >> 2);
        #pragma unroll
        for (int nt = 0; nt < 8; ++nt) {
            const int col = bcol + n0 + nt * 8 + (lane & 3) * 2;
            const float b0 = bias[col], b1 = bias[col + 1];
            const float v0 = acc[mt][nt][0] + b0, v1 = acc[mt][nt][1] + b1;
            const float v2 = acc[mt][nt][2] + b0, v3 = acc[mt][nt][3] + b1;
            if (SPLIT) {
                uint32_t hp, lp;
                split_pack2(v0, v1, hp, lp);
                *(uint32_t*)(Ch + (size_t)r0 * N + col) = hp;
                *(uint32_t*)(Cl + (size_t)r0 * N + col) = lp;
                split_pack2(v2, v3, hp, lp);
                *(uint32_t*)(Ch + (size_t)(r0 + 8) * N + col) = hp;
                *(uint32_t*)(Cl + (size_t)(r0 + 8) * N + col) = lp;
            } else {
                *(float2*)(C + (size_t)r0 * N + col) = make_float2(v0, v1);
                *(float2*)(C + (size_t)(r0 + 8) * N + col) = make_float2(v2, v3);
            }
        }
    }
}

// ---------------------------------------------------------------------------
// Flash attention via mma.sync (bf16 hi/lo 3-term), causal.
// CTA: 128 queries of one (b,h). 8 warps x 16 q-rows. KV tile 64, dbl-buffered.
// ---------------------------------------------------------------------------
#define FBQ   128
#define FBKV  64
#define FQH_O 0
#define FQL_O 32768
#define FSTG  65536
#define FSTGSZ 65536
#define FKH_O 0
#define FKL_O 16384
#define FVH_O 32768
#define FVL_O 49152
#define FSMEM (FSTG + 2 * FSTGSZ)   // 196608

// 256B rows (128 bf16), 16B chunk swizzle
__device__ __forceinline__ uint32_t swzf(int r, int c) {
    return (uint32_t)(r * 256 + ((c ^ (r & 7)) << 4));
}

__global__ __launch_bounds__(256)
void flash_mma_kernel(const __nv_bfloat16* __restrict__ qkvh,
                      const __nv_bfloat16* __restrict__ qkvl,
                      __nv_bfloat16* __restrict__ oh,
                      __nv_bfloat16* __restrict__ ol)
{
    extern __shared__ char smem[];
    const uint32_t sb = smem_u32(smem);
    const int tid  = threadIdx.x;
    const int lane = tid & 31;
    const int wid  = tid >> 5;
    const int qb   = blockIdx.x;        // 0..7
    const int bh   = blockIdx.y;        // 0..63
    const int b    = bh >> 4;
    const int h    = bh & 15;
    const int m0   = wid * 16;
    const int tokQ = b * TT + qb * FBQ;
    const float scale = 0.08838834764831845f;   // 1/sqrt(128)

    // ---- Load Q tiles (hi/lo), 8 chunks per thread each
    {
        #pragma unroll
        for (int i = 0; i < 8; ++i) {
            const int idx = i * 256 + tid;
            const int r = idx >> 4, c = idx & 15;
            const uint32_t o = swzf(r, c);
            const size_t g = (size_t)(tokQ + r) * NQKV + h * HDIM + c * 8;
            cp16(sb + FQH_O + o, qkvh + g);
            cp16(sb + FQL_O + o, qkvl + g);
        }
    }
    // ---- Load KV stage 0 (j=0)
    const int jmax = 2 * qb + 1;
    {
        #pragma unroll
        for (int i = 0; i < 4; ++i) {
            const int idx = i * 256 + tid;
            const int r = idx >> 4, c = idx & 15;
            const uint32_t o = swzf(r, c);
            const size_t gk = (size_t)(b * TT + r) * NQKV + DMODEL + h * HDIM + c * 8;
            const size_t gv = gk + DMODEL;
            cp16(sb + FSTG + FKH_O + o, qkvh + gk);
            cp16(sb + FSTG + FKL_O + o, qkvl + gk);
            cp16(sb + FSTG + FVH_O + o, qkvh + gv);
            cp16(sb + FSTG + FVL_O + o, qkvl + gv);
        }
    }
    cp_commit();

    float m_[2] = {-1e30f, -1e30f};
    float l_[2] = {0.0f, 0.0f};
    float o_[16][4];
    #pragma unroll
    for (int ng = 0; ng < 16; ++ng)
        #pragma unroll
        for (int i = 0; i < 4; ++i) o_[ng][i] = 0.0f;

    const int qrow0 = qb * FBQ + m0 + (lane >> 2);

    for (int j = 0; j <= jmax; ++j) {
        // prefetch j+1 into other stage
        if (j < jmax) {
            const uint32_t stb = sb + FSTG + (uint32_t)((j + 1) & 1) * FSTGSZ;
            #pragma unroll
            for (int i = 0; i < 4; ++i) {
                const int idx = i * 256 + tid;
                const int r = idx >> 4, c = idx & 15;
                const uint32_t o = swzf(r, c);
                const size_t gk = (size_t)(b * TT + (j + 1) * FBKV + r) * NQKV
                                + DMODEL + h * HDIM + c * 8;
                const size_t gv = gk + DMODEL;
                cp16(stb + FKH_O + o, qkvh + gk);
                cp16(stb + FKL_O + o, qkvl + gk);
                cp16(stb + FVH_O + o, qkvh + gv);
                cp16(stb + FVL_O + o, qkvl + gv);
            }
        }
        cp_commit();
        if (j < jmax) cp_wait1(); else cp_wait0();
        __syncthreads();

        const uint32_t st = sb + FSTG + (uint32_t)(j & 1) * FSTGSZ;

        // ---- S = Q K^T (3-term) : s[8][4] per thread (16 rows x 64 cols / warp)
        float s[8][4];
        #pragma unroll
        for (int nt = 0; nt < 8; ++nt)
            #pragma unroll
            for (int i = 0; i < 4; ++i) s[nt][i] = 0.0f;

        #pragma unroll
        for (int kc = 0; kc < 8; ++kc) {
            uint32_t qH[4], qL[4];
            const uint32_t qa = sb + swzf(m0 + (lane & 15), 2 * kc + (lane >> 4));
            ldsm4(qH, qa + FQH_O);
            ldsm4(qL, qa + FQL_O);
            #pragma unroll
            for (int p = 0; p < 4; ++p) {
                uint32_t kH[4], kL[4];
                const uint32_t ka = st + swzf(p * 16 + (lane & 15), 2 * kc + (lane >> 4));
                ldsm4(kH, ka + FKH_O);
                ldsm4(kL, ka + FKL_O);
                #pragma unroll
                for (int sub = 0; sub < 2; ++sub) {
                    const int nt = 2 * p + sub;
                    mma16816(s[nt], qH, kH[sub], kH[sub + 2]);
                    mma16816(s[nt], qH, kL[sub], kL[sub + 2]);
                    mma16816(s[nt], qL, kH[sub], kH[sub + 2]);
                }
            }
        }

        // scale + causal mask
        #pragma unroll
        for (int nt = 0; nt < 8; ++nt)
            #pragma unroll
            for (int i = 0; i < 4; ++i) s[nt][i] *= scale;
        if (j >= 2 * qb) {
            const int kb = j * FBKV + ((lane & 3) << 1);
            #pragma unroll
            for (int nt = 0; nt < 8; ++nt) {
                const int k0 = kb + nt * 8, k1 = k0 + 1;
                if (k0 > qrow0)     s[nt][0] = -1e30f;
                if (k1 > qrow0)     s[nt][1] = -1e30f;
                if (k0 > qrow0 + 8) s[nt][2] = -1e30f;
                if (k1 > qrow0 + 8) s[nt][3] = -1e30f;
            }
        }

        // ---- online softmax (rows r, r+8)
        float mx0 = -1e30f, mx1 = -1e30f;
        #pragma unroll
        for (int nt = 0; nt < 8; ++nt) {
            mx0 = fmaxf(mx0, fmaxf(s[nt][0], s[nt][1]));
            mx1 = fmaxf(mx1, fmaxf(s[nt][2], s[nt][3]));
        }
        mx0 = fmaxf(mx0, __shfl_xor_sync(0xffffffffu, mx0, 1));
        mx0 = fmaxf(mx0, __shfl_xor_sync(0xffffffffu, mx0, 2));
        mx1 = fmaxf(mx1, __shfl_xor_sync(0xffffffffu, mx1, 1));
        mx1 = fmaxf(mx1, __shfl_xor_sync(0xffffffffu, mx1, 2));
        const float mn0 = fmaxf(m_[0], mx0);
        const float mn1 = fmaxf(m_[1], mx1);
        const float a0 = __expf(m_[0] - mn0);
        const float a1 = __expf(m_[1] - mn1);
        float sum0 = 0.0f, sum1 = 0.0f;
        #pragma unroll
        for (int nt = 0; nt < 8; ++nt) {
            s[nt][0] = __expf(s[nt][0] - mn0); sum0 += s[nt][0];
            s[nt][1] = __expf(s[nt][1] - mn0); sum0 += s[nt][1];
            s[nt][2] = __expf(s[nt][2] - mn1); sum1 += s[nt][2];
            s[nt][3] = __expf(s[nt][3] - mn1); sum1 += s[nt][3];
        }
        sum0 += __shfl_xor_sync(0xffffffffu, sum0, 1);
        sum0 += __shfl_xor_sync(0xffffffffu, sum0, 2);
        sum1 += __shfl_xor_sync(0xffffffffu, sum1, 1);
        sum1 += __shfl_xor_sync(0xffffffffu, sum1, 2);
        l_[0] = l_[0] * a0 + sum0;
        l_[1] = l_[1] * a1 + sum1;
        m_[0] = mn0; m_[1] = mn1;
        #pragma unroll
        for (int ng = 0; ng < 16; ++ng) {
            o_[ng][0] *= a0; o_[ng][1] *= a0;
            o_[ng][2] *= a1; o_[ng][3] *= a1;
        }

        // ---- O += P V (3-term). P frags from S c-layout.
        #pragma unroll
        for (int kt = 0; kt < 4; ++kt) {
            uint32_t pH[4], pL[4];
            split_pack2(s[2 * kt][0],     s[2 * kt][1],     pH[0], pL[0]);
            split_pack2(s[2 * kt][2],     s[2 * kt][3],     pH[1], pL[1]);
            split_pack2(s[2 * kt + 1][0], s[2 * kt + 1][1], pH[2], pL[2]);
            split_pack2(s[2 * kt + 1][2], s[2 * kt + 1][3], pH[3], pL[3]);
            #pragma unroll
            for (int g2 = 0; g2 < 8; ++g2) {
                uint32_t vH[4], vL[4];
                const uint32_t va = st + swzf(kt * 16 + (lane & 15), 2 * g2 + (lane >> 4));
                ldsm4t(vH, va + FVH_O);
                ldsm4t(vL, va + FVL_O);
                #pragma unroll
                for (int sub = 0; sub < 2; ++sub) {
                    const int ng = 2 * g2 + sub;
                    mma16816(o_[ng], pH, vH[2 * sub], vH[2 * sub + 1]);
                    mma16816(o_[ng], pH, vL[2 * sub], vL[2 * sub + 1]);
                    mma16816(o_[ng], pL, vH[2 * sub], vH[2 * sub + 1]);
                }
            }
        }
        __syncthreads();
    }

    // ---- epilogue: normalize + split-write bf16 hi/lo
    const float inv0 = 1.0f / l_[0];
    const float inv1 = 1.0f / l_[1];
    const size_t tok0 = (size_t)tokQ + m0 + (lane >> 2);
    #pragma unroll
    for (int ng = 0; ng < 16; ++ng) {
        const int col = h * HDIM + ng * 8 + ((lane & 3) << 1);
        uint32_t hp, lp;
        split_pack2(o_[ng][0] * inv0, o_[ng][1] * inv0, hp, lp);
        *(uint32_t*)(oh + tok0 * DMODEL + col) = hp;
        *(uint32_t*)(ol + tok0 * DMODEL + col) = lp;
        split_pack2(o_[ng][2] * inv1, o_[ng][3] * inv1, hp, lp);
        *(uint32_t*)(oh + (tok0 + 8) * DMODEL + col) = hp;
        *(uint32_t*)(ol + (tok0 + 8) * DMODEL + col) = lp;
    }
}

// ---------------------------------------------------------------------------
extern "C" void kernel_launch(void* const* d_in, const int* in_sizes, int n_in,
                              void* d_out, int out_size)
{
    (void)in_sizes; (void)n_in; (void)out_size;
    const float* x      = (const float*)d_in[0];
    const float* w_qkv  = (const float*)d_in[1];
    const float* b_qkv  = (const float*)d_in[2];
    const float* w_out  = (const float*)d_in[3];
    const float* b_out  = (const float*)d_in[4];
    float* out          = (float*)d_out;

    void *xh, *xl, *wqh, *wql, *woh, *wol, *qvh, *qvl, *ath, *atl;
    cudaGetSymbolAddress(&xh, g_xh);
    cudaGetSymbolAddress(&xl, g_xl);
    cudaGetSymbolAddress(&wqh, g_wqt_h);
    cudaGetSymbolAddress(&wql, g_wqt_l);
    cudaGetSymbolAddress(&woh, g_wot_h);
    cudaGetSymbolAddress(&wol, g_wot_l);
    cudaGetSymbolAddress(&qvh, g_qkvh);
    cudaGetSymbolAddress(&qvl, g_qkvl);
    cudaGetSymbolAddress(&ath, g_ath);
    cudaGetSymbolAddress(&atl, g_atl);

    cudaFuncSetAttribute(gemm_bf16x3_kernel<true>,
                         cudaFuncAttributeMaxDynamicSharedMemorySize, GSMEM);
    cudaFuncSetAttribute(gemm_bf16x3_kernel<false>,
                         cudaFuncAttributeMaxDynamicSharedMemorySize, GSMEM);
    cudaFuncSetAttribute(flash_mma_kernel,
                         cudaFuncAttributeMaxDynamicSharedMemorySize, FSMEM);

    // Split x
    {
        const int n4 = MTOK * DMODEL / 4;
        split_kernel<<<(n4 + 255) / 256, 256>>>(x, (__nv_bfloat16*)xh,
                                                (__nv_bfloat16*)xl, n4);
    }
    // Transpose + split weights
    {
        dim3 blk(32, 8);
        transpose_split_kernel<<<dim3(NQKV / 32, DMODEL / 32), blk>>>(
            w_qkv, (__nv_bfloat16*)wqh, (__nv_bfloat16*)wql, DMODEL, NQKV);
        transpose_split_kernel<<<dim3(DMODEL / 32, DMODEL / 32), blk>>>(
            w_out, (__nv_bfloat16*)woh, (__nv_bfloat16*)wol, DMODEL, DMODEL);
    }
    // 1) QKV projection -> bf16 hi/lo (split epilogue)
    {
        dim3 grid(NQKV / 128, MTOK / 128);
        gemm_bf16x3_kernel<true><<<grid, 256, GSMEM>>>(
            (const __nv_bfloat16*)xh, (const __nv_bfloat16*)xl,
            (const __nv_bfloat16*)wqh, (const __nv_bfloat16*)wql,
            b_qkv, nullptr, (__nv_bfloat16*)qvh, (__nv_bfloat16*)qvl, NQKV);
    }
    // 2) Causal flash attention (tensor cores) -> bf16 hi/lo
    {
        dim3 grid(TT / FBQ, BB * NHEADS);
        flash_mma_kernel<<<grid, 256, FSMEM>>>(
            (const __nv_bfloat16*)qvh, (const __nv_bfloat16*)qvl,
            (__nv_bfloat16*)ath, (__nv_bfloat16*)atl);
    }
    // 3) Output projection -> fp32 out
    {
        dim3 grid(DMODEL / 128, MTOK / 128);
        gemm_bf16x3_kernel<false><<<grid, 256, GSMEM>>>(
            (const __nv_bfloat16*)ath, (const __nv_bfloat16*)atl,
            (const __nv_bfloat16*)woh, (const __nv_bfloat16*)wol,
            b_out, out, nullptr, nullptr, DMODEL);
    }
}